// round 16
// baseline (speedup 1.0000x reference)
#include <cuda_runtime.h>
#include <cuda_fp16.h>
#include <math.h>
#include <stdint.h>

#define N 4096
#define D 2048
#define MARGIN 0.3f

// ---------------------------------------------------------------------------
// Device globals (no allocation allowed)
// ---------------------------------------------------------------------------
__device__ __half g_Hf[(size_t)N * D];   // fp16-rounded copy of features
__device__ float g_sq[N];
__device__ int   g_lab[N];
__device__ float g_ap[N];                // max d^2 (positive)
__device__ float g_an[N];                // min d^2 (negative)
__device__ unsigned g_done;              // finished-CTA ticket

// ---------------------------------------------------------------------------
// Kernel 1: warp-per-row fp32->fp16 + norms + init
// ---------------------------------------------------------------------------
__global__ __launch_bounds__(256)
void prep_kernel(const float* __restrict__ F,
                 const int* __restrict__ lab) {
    const int row  = blockIdx.x * 8 + (threadIdx.x >> 5);
    const int lane = threadIdx.x & 31;
    const float4* f4 = reinterpret_cast<const float4*>(F + (size_t)row * D);
    __half2* h2 = reinterpret_cast<__half2*>(g_Hf + (size_t)row * D);
    float s = 0.f;
    #pragma unroll
    for (int i = 0; i < 16; i++) {
        int k = lane + i * 32;
        float4 v = f4[k];
        s += v.x * v.x + v.y * v.y + v.z * v.z + v.w * v.w;
        h2[k * 2 + 0] = __floats2half2_rn(v.x, v.y);
        h2[k * 2 + 1] = __floats2half2_rn(v.z, v.w);
    }
    #pragma unroll
    for (int o = 16; o; o >>= 1) s += __shfl_xor_sync(0xffffffffu, s, o);
    if (lane == 0) {
        g_sq[row]  = s;
        g_lab[row] = lab[row];
        g_ap[row]  = 0.f;
        g_an[row]  = __int_as_float(0x7f800000);
        if (row == 0) g_done = 0;
    }
}

// ---------------------------------------------------------------------------
// Kernel 2: fp16 mma.sync Gram tile 64x128, 128 threads, 3 CTAs/SM,
// ks-level fragment double-buffering (R12 loop). Tile set {bi >= 2*bj};
// two-way mining on SQUARED distances (sqrt deferred to final reduction).
// Last CTA to finish computes the final scalar loss.
// ---------------------------------------------------------------------------
#define TM 64
#define TN 128
#define KCH 64                        // fp16 elements per K chunk (=128B/row)
#define NCHUNK (D / KCH)              // 32
#define ROWB 144                      // padded row bytes (128 data + 16 pad)
#define A_BYTES (TM * ROWB)           // 9216
#define B_BYTES (TN * ROWB)           // 18432
#define STAGEB (A_BYTES + B_BYTES)    // 27648
#define NBLK 1056                     // sum_{bj=0}^{31} (64 - 2*bj)

#define OFF_RSQ (2 * STAGEB)
#define OFF_RLB (OFF_RSQ + 256)
#define OFF_CSQ (OFF_RLB + 256)
#define OFF_CLB (OFF_CSQ + 512)
#define SMEM_BYTES (OFF_CLB + 512)    // 56832

__device__ __forceinline__ uint32_t smem_u32(const void* p) {
    uint32_t a;
    asm("{ .reg .u64 t; cvta.to.shared.u64 t, %1; cvt.u32.u64 %0, t; }" : "=r"(a) : "l"(p));
    return a;
}
__device__ __forceinline__ void cp16(uint32_t dst, const void* src) {
    asm volatile("cp.async.cg.shared.global [%0], [%1], 16;" :: "r"(dst), "l"(src));
}
__device__ __forceinline__ void cp_commit() {
    asm volatile("cp.async.commit_group;" ::: "memory");
}
__device__ __forceinline__ void ldsm_x4(uint32_t& r0, uint32_t& r1, uint32_t& r2,
                                        uint32_t& r3, uint32_t addr) {
    asm volatile("ldmatrix.sync.aligned.m8n8.x4.shared.b16 {%0,%1,%2,%3}, [%4];"
                 : "=r"(r0), "=r"(r1), "=r"(r2), "=r"(r3) : "r"(addr));
}
__device__ __forceinline__ void mma_f16(float* c, uint32_t a0, uint32_t a1,
                                        uint32_t a2, uint32_t a3,
                                        uint32_t b0, uint32_t b1) {
    asm volatile("mma.sync.aligned.m16n8k16.row.col.f32.f16.f16.f32 "
                 "{%0,%1,%2,%3}, {%4,%5,%6,%7}, {%8,%9}, {%0,%1,%2,%3};"
                 : "+f"(c[0]), "+f"(c[1]), "+f"(c[2]), "+f"(c[3])
                 : "r"(a0), "r"(a1), "r"(a2), "r"(a3), "r"(b0), "r"(b1));
}

__global__ __launch_bounds__(128, 3)
void mma_mine_kernel(float* __restrict__ out) {
    extern __shared__ char sb[];
    const uint32_t sbase = smem_u32(sb);
    const int tid  = threadIdx.x;
    const int lane = tid & 31;
    const int wid  = tid >> 5;
    const int wm   = wid >> 1;
    const int wn   = wid & 1;

    int t = blockIdx.x;
    int bj = 0, s = 0;
    while (s + (64 - 2 * bj) <= t) { s += 64 - 2 * bj; bj++; }
    int bi = 2 * bj + (t - s);

    const int rowBase = bi * TM;
    const int colBase = bj * TN;

    if (tid < 64) {
        ((float*)(sb + OFF_RSQ))[tid] = g_sq[rowBase + tid];
        ((int*)(sb + OFF_RLB))[tid]   = g_lab[rowBase + tid];
    }
    ((float*)(sb + OFF_CSQ))[tid] = g_sq[colBase + tid];
    ((int*)(sb + OFF_CLB))[tid]   = g_lab[colBase + tid];

    const int ldR = tid >> 3;
    const int ldQ = tid & 7;

    auto issue = [&](int c) {
        const int kc = c * KCH;
        const uint32_t st = sbase + (c & 1) * STAGEB;
        #pragma unroll
        for (int i = 0; i < 4; i++) {
            int r = ldR + i * 16;
            cp16(st + r * ROWB + ldQ * 16,
                 g_Hf + (size_t)(rowBase + r) * D + kc + ldQ * 8);
        }
        #pragma unroll
        for (int i = 0; i < 8; i++) {
            int r = ldR + i * 16;
            cp16(st + A_BYTES + r * ROWB + ldQ * 16,
                 g_Hf + (size_t)(colBase + r) * D + kc + ldQ * 8);
        }
        cp_commit();
    };

    uint32_t aOff[2];
    #pragma unroll
    for (int mi = 0; mi < 2; mi++) {
        int r = wm * 32 + mi * 16 + (lane & 15);
        aOff[mi] = r * ROWB + (lane >> 4) * 16;
    }
    uint32_t bOff[4];
    {
        int mat = lane >> 3;
        #pragma unroll
        for (int nt = 0; nt < 4; nt++) {
            int n = wn * 64 + nt * 16 + ((mat & 2) << 2) + (lane & 7);
            bOff[nt] = A_BYTES + n * ROWB + (mat & 1) * 16;
        }
    }

    float acc[2][8][4];
    #pragma unroll
    for (int mi = 0; mi < 2; mi++)
        #pragma unroll
        for (int ni = 0; ni < 8; ni++)
            #pragma unroll
            for (int r = 0; r < 4; r++) acc[mi][ni][r] = 0.f;

    // double-buffered fragments (parity = ks & 1)
    uint32_t fa[2][2][4];
    uint32_t fb[2][8][2];

    auto ldfrag = [&](int par, uint32_t st, int ks) {
        #pragma unroll
        for (int mi = 0; mi < 2; mi++)
            ldsm_x4(fa[par][mi][0], fa[par][mi][1], fa[par][mi][2], fa[par][mi][3],
                    st + aOff[mi] + ks * 32);
        #pragma unroll
        for (int nt = 0; nt < 4; nt++) {
            uint32_t r0, r1, r2, r3;
            ldsm_x4(r0, r1, r2, r3, st + bOff[nt] + ks * 32);
            fb[par][nt * 2 + 0][0] = r0; fb[par][nt * 2 + 0][1] = r1;
            fb[par][nt * 2 + 1][0] = r2; fb[par][nt * 2 + 1][1] = r3;
        }
    };
    auto domma = [&](int par) {
        #pragma unroll
        for (int mi = 0; mi < 2; mi++)
            #pragma unroll
            for (int ni = 0; ni < 8; ni++)
                mma_f16(acc[mi][ni],
                        fa[par][mi][0], fa[par][mi][1], fa[par][mi][2], fa[par][mi][3],
                        fb[par][ni][0], fb[par][ni][1]);
    };

    issue(0); issue(1);
    asm volatile("cp.async.wait_group 1;" ::: "memory");
    __syncthreads();                      // stage 0 visible to all warps
    ldfrag(0, sbase, 0);

    for (int c = 0; c < NCHUNK; c++) {
        const uint32_t st = sbase + (c & 1) * STAGEB;
        #pragma unroll
        for (int ks = 0; ks < 4; ks++) {
            if (ks < 3) ldfrag((ks + 1) & 1, st, ks + 1);
            domma(ks & 1);
        }
        __syncthreads();                  // all warps done reading stage c
        if (c + 1 < NCHUNK) {
            if (c + 2 < NCHUNK) {
                issue(c + 2);
                asm volatile("cp.async.wait_group 1;" ::: "memory");
            } else {
                asm volatile("cp.async.wait_group 0;" ::: "memory");
            }
            __syncthreads();              // publish stage c+1
            ldfrag(0, sbase + ((c + 1) & 1) * STAGEB, 0);
        }
    }

    // ------------- epilogue: squared-distance two-way mining -------------
    const float* rsq = (const float*)(sb + OFF_RSQ);
    const int*   rlb = (const int*)(sb + OFF_RLB);
    const float* csq = (const float*)(sb + OFF_CSQ);
    const int*   clb = (const int*)(sb + OFF_CLB);

    const float INF = __int_as_float(0x7f800000);

    float apv[2][2], anv[2][2];
    float sqr[2][2]; int lbr[2][2];
    #pragma unroll
    for (int mi = 0; mi < 2; mi++)
        #pragma unroll
        for (int h = 0; h < 2; h++) {
            apv[mi][h] = 0.f;
            anv[mi][h] = INF;
            int r = wm * 32 + mi * 16 + h * 8 + (lane >> 2);
            sqr[mi][h] = rsq[r];
            lbr[mi][h] = rlb[r];
        }

    #pragma unroll
    for (int ni = 0; ni < 8; ni++) {
        const int jl = wn * 64 + ni * 8 + (lane & 3) * 2;
        float cap[2] = {0.f, 0.f};
        float can[2] = {INF, INF};
        #pragma unroll
        for (int e = 0; e < 2; e++) {
            const float sqj = csq[jl + e];
            const int   lj  = clb[jl + e];
            #pragma unroll
            for (int mi = 0; mi < 2; mi++)
                #pragma unroll
                for (int h = 0; h < 2; h++) {
                    float d2 = fmaf(-2.f, acc[mi][ni][h * 2 + e], sqr[mi][h] + sqj);
                    d2 = fmaxf(d2, 0.f);       // clamp; sqrt deferred (monotone)
                    if (lbr[mi][h] == lj) {
                        apv[mi][h] = fmaxf(apv[mi][h], d2);
                        cap[e] = fmaxf(cap[e], d2);
                    } else {
                        anv[mi][h] = fminf(anv[mi][h], d2);
                        can[e] = fminf(can[e], d2);
                    }
                }
        }
        // column mining (mirrored extras are idempotent for max/min)
        #pragma unroll
        for (int e = 0; e < 2; e++) {
            #pragma unroll
            for (int o = 4; o <= 16; o <<= 1) {
                cap[e] = fmaxf(cap[e], __shfl_xor_sync(0xffffffffu, cap[e], o));
                can[e] = fminf(can[e], __shfl_xor_sync(0xffffffffu, can[e], o));
            }
            if (lane < 4) {
                int col = colBase + wn * 64 + ni * 8 + lane * 2 + e;
                atomicMax((int*)&g_ap[col], __float_as_int(cap[e]));
                atomicMin((int*)&g_an[col], __float_as_int(can[e]));
            }
        }
    }

    // row-side reduction over 4 lanes sharing each row
    #pragma unroll
    for (int mi = 0; mi < 2; mi++)
        #pragma unroll
        for (int h = 0; h < 2; h++) {
            #pragma unroll
            for (int o = 1; o <= 2; o <<= 1) {
                apv[mi][h] = fmaxf(apv[mi][h], __shfl_xor_sync(0xffffffffu, apv[mi][h], o));
                anv[mi][h] = fminf(anv[mi][h], __shfl_xor_sync(0xffffffffu, anv[mi][h], o));
            }
        }
    if ((lane & 3) == 0) {
        #pragma unroll
        for (int mi = 0; mi < 2; mi++)
            #pragma unroll
            for (int h = 0; h < 2; h++) {
                int row = rowBase + wm * 32 + mi * 16 + h * 8 + (lane >> 2);
                atomicMax((int*)&g_ap[row], __float_as_int(apv[mi][h]));
                atomicMin((int*)&g_an[row], __float_as_int(anv[mi][h]));
            }
    }

    // ------------- fused final loss: last CTA reduces (sqrt here) -------------
    __syncthreads();
    __shared__ unsigned s_rank;
    if (tid == 0) {
        __threadfence();
        s_rank = atomicAdd(&g_done, 1u);
    }
    __syncthreads();
    if (s_rank == NBLK - 1) {
        __threadfence();
        float* ssum = (float*)(sb);
        int*   scnt = (int*)(sb + 1024);
        float s2 = 0.f; int c = 0;
        for (int i = tid; i < N; i += 128) {
            float ap2 = g_ap[i];
            float an2 = g_an[i];
            if (ap2 > 0.f && isfinite(an2)) {
                c++;
                float v = sqrtf(ap2) - sqrtf(an2) + MARGIN;
                s2 += v > 0.f ? v : 0.f;
            }
        }
        ssum[tid] = s2;
        scnt[tid] = c;
        __syncthreads();
        for (int o = 64; o; o >>= 1) {
            if (tid < o) {
                ssum[tid] += ssum[tid + o];
                scnt[tid] += scnt[tid + o];
            }
            __syncthreads();
        }
        if (tid == 0) {
            int n = scnt[0];
            out[0] = (n > 0) ? (ssum[0] / (float)n) : 0.f;
        }
    }
}

// ---------------------------------------------------------------------------
extern "C" void kernel_launch(void* const* d_in, const int* in_sizes, int n_in,
                              void* d_out, int out_size) {
    const float* F   = (const float*)d_in[0];
    const int*   lab = (const int*)d_in[1];
    float* out = (float*)d_out;

    cudaFuncSetAttribute(mma_mine_kernel,
                         cudaFuncAttributeMaxDynamicSharedMemorySize, SMEM_BYTES);

    prep_kernel<<<N / 8, 256>>>(F, lab);
    mma_mine_kernel<<<NBLK, 128, SMEM_BYTES>>>(out);
}

// round 17
// speedup vs baseline: 1.0040x; 1.0040x over previous
#include <cuda_runtime.h>
#include <cuda_fp16.h>
#include <math.h>
#include <stdint.h>

#define N 4096
#define D 2048
#define MARGIN 0.3f

// ---------------------------------------------------------------------------
// Device globals (no allocation allowed)
// ---------------------------------------------------------------------------
__device__ __half g_Hf[(size_t)N * D];   // fp16-rounded copy of features
__device__ float g_sq[N];
__device__ int   g_lab[N];
__device__ float g_ap[N];                // max d^2 (positive)
__device__ float g_an[N];                // min d^2 (negative)
__device__ unsigned g_done;              // finished-CTA ticket

// ---------------------------------------------------------------------------
// Kernel 1: warp-per-row fp32->fp16 + norms + init
// ---------------------------------------------------------------------------
__global__ __launch_bounds__(256)
void prep_kernel(const float* __restrict__ F,
                 const int* __restrict__ lab) {
    const int row  = blockIdx.x * 8 + (threadIdx.x >> 5);
    const int lane = threadIdx.x & 31;
    const float4* f4 = reinterpret_cast<const float4*>(F + (size_t)row * D);
    __half2* h2 = reinterpret_cast<__half2*>(g_Hf + (size_t)row * D);
    float s = 0.f;
    #pragma unroll
    for (int i = 0; i < 16; i++) {
        int k = lane + i * 32;
        float4 v = f4[k];
        s += v.x * v.x + v.y * v.y + v.z * v.z + v.w * v.w;
        h2[k * 2 + 0] = __floats2half2_rn(v.x, v.y);
        h2[k * 2 + 1] = __floats2half2_rn(v.z, v.w);
    }
    #pragma unroll
    for (int o = 16; o; o >>= 1) s += __shfl_xor_sync(0xffffffffu, s, o);
    if (lane == 0) {
        g_sq[row]  = s;
        g_lab[row] = lab[row];
        g_ap[row]  = 0.f;
        g_an[row]  = __int_as_float(0x7f800000);
        if (row == 0) g_done = 0;
    }
}

// ---------------------------------------------------------------------------
// Kernel 2: fp16 mma.sync Gram tile 64x128, 128 threads, 3 CTAs/SM,
// ks-level fragment double-buffering (R12 loop). Tile set {bi >= 2*bj};
// two-way mining on SQUARED distances (sqrt deferred to final reduction).
// Last CTA to finish computes the final scalar loss.
// ---------------------------------------------------------------------------
#define TM 64
#define TN 128
#define KCH 64                        // fp16 elements per K chunk (=128B/row)
#define NCHUNK (D / KCH)              // 32
#define ROWB 144                      // padded row bytes (128 data + 16 pad)
#define A_BYTES (TM * ROWB)           // 9216
#define B_BYTES (TN * ROWB)           // 18432
#define STAGEB (A_BYTES + B_BYTES)    // 27648
#define NBLK 1056                     // sum_{bj=0}^{31} (64 - 2*bj)

#define OFF_RSQ (2 * STAGEB)
#define OFF_RLB (OFF_RSQ + 256)
#define OFF_CSQ (OFF_RLB + 256)
#define OFF_CLB (OFF_CSQ + 512)
#define SMEM_BYTES (OFF_CLB + 512)    // 56832

__device__ __forceinline__ uint32_t smem_u32(const void* p) {
    uint32_t a;
    asm("{ .reg .u64 t; cvta.to.shared.u64 t, %1; cvt.u32.u64 %0, t; }" : "=r"(a) : "l"(p));
    return a;
}
__device__ __forceinline__ void cp16(uint32_t dst, const void* src) {
    asm volatile("cp.async.cg.shared.global [%0], [%1], 16;" :: "r"(dst), "l"(src));
}
__device__ __forceinline__ void cp_commit() {
    asm volatile("cp.async.commit_group;" ::: "memory");
}
__device__ __forceinline__ void ldsm_x4(uint32_t& r0, uint32_t& r1, uint32_t& r2,
                                        uint32_t& r3, uint32_t addr) {
    asm volatile("ldmatrix.sync.aligned.m8n8.x4.shared.b16 {%0,%1,%2,%3}, [%4];"
                 : "=r"(r0), "=r"(r1), "=r"(r2), "=r"(r3) : "r"(addr));
}
__device__ __forceinline__ void mma_f16(float* c, uint32_t a0, uint32_t a1,
                                        uint32_t a2, uint32_t a3,
                                        uint32_t b0, uint32_t b1) {
    asm volatile("mma.sync.aligned.m16n8k16.row.col.f32.f16.f16.f32 "
                 "{%0,%1,%2,%3}, {%4,%5,%6,%7}, {%8,%9}, {%0,%1,%2,%3};"
                 : "+f"(c[0]), "+f"(c[1]), "+f"(c[2]), "+f"(c[3])
                 : "r"(a0), "r"(a1), "r"(a2), "r"(a3), "r"(b0), "r"(b1));
}

__global__ __launch_bounds__(128, 3)
void mma_mine_kernel(float* __restrict__ out) {
    extern __shared__ char sb[];
    const uint32_t sbase = smem_u32(sb);
    const int tid  = threadIdx.x;
    const int lane = tid & 31;
    const int wid  = tid >> 5;
    const int wm   = wid >> 1;
    const int wn   = wid & 1;

    int t = blockIdx.x;
    int bj = 0, s = 0;
    while (s + (64 - 2 * bj) <= t) { s += 64 - 2 * bj; bj++; }
    int bi = 2 * bj + (t - s);

    const int rowBase = bi * TM;
    const int colBase = bj * TN;

    if (tid < 64) {
        ((float*)(sb + OFF_RSQ))[tid] = g_sq[rowBase + tid];
        ((int*)(sb + OFF_RLB))[tid]   = g_lab[rowBase + tid];
    }
    ((float*)(sb + OFF_CSQ))[tid] = g_sq[colBase + tid];
    ((int*)(sb + OFF_CLB))[tid]   = g_lab[colBase + tid];

    const int ldR = tid >> 3;
    const int ldQ = tid & 7;

    auto issue = [&](int c) {
        const int kc = c * KCH;
        const uint32_t st = sbase + (c & 1) * STAGEB;
        #pragma unroll
        for (int i = 0; i < 4; i++) {
            int r = ldR + i * 16;
            cp16(st + r * ROWB + ldQ * 16,
                 g_Hf + (size_t)(rowBase + r) * D + kc + ldQ * 8);
        }
        #pragma unroll
        for (int i = 0; i < 8; i++) {
            int r = ldR + i * 16;
            cp16(st + A_BYTES + r * ROWB + ldQ * 16,
                 g_Hf + (size_t)(colBase + r) * D + kc + ldQ * 8);
        }
        cp_commit();
    };

    uint32_t aOff[2];
    #pragma unroll
    for (int mi = 0; mi < 2; mi++) {
        int r = wm * 32 + mi * 16 + (lane & 15);
        aOff[mi] = r * ROWB + (lane >> 4) * 16;
    }
    uint32_t bOff[4];
    {
        int mat = lane >> 3;
        #pragma unroll
        for (int nt = 0; nt < 4; nt++) {
            int n = wn * 64 + nt * 16 + ((mat & 2) << 2) + (lane & 7);
            bOff[nt] = A_BYTES + n * ROWB + (mat & 1) * 16;
        }
    }

    float acc[2][8][4];
    #pragma unroll
    for (int mi = 0; mi < 2; mi++)
        #pragma unroll
        for (int ni = 0; ni < 8; ni++)
            #pragma unroll
            for (int r = 0; r < 4; r++) acc[mi][ni][r] = 0.f;

    // double-buffered fragments (parity = ks & 1)
    uint32_t fa[2][2][4];
    uint32_t fb[2][8][2];

    auto ldfrag = [&](int par, uint32_t st, int ks) {
        #pragma unroll
        for (int mi = 0; mi < 2; mi++)
            ldsm_x4(fa[par][mi][0], fa[par][mi][1], fa[par][mi][2], fa[par][mi][3],
                    st + aOff[mi] + ks * 32);
        #pragma unroll
        for (int nt = 0; nt < 4; nt++) {
            uint32_t r0, r1, r2, r3;
            ldsm_x4(r0, r1, r2, r3, st + bOff[nt] + ks * 32);
            fb[par][nt * 2 + 0][0] = r0; fb[par][nt * 2 + 0][1] = r1;
            fb[par][nt * 2 + 1][0] = r2; fb[par][nt * 2 + 1][1] = r3;
        }
    };
    auto domma = [&](int par) {
        #pragma unroll
        for (int mi = 0; mi < 2; mi++)
            #pragma unroll
            for (int ni = 0; ni < 8; ni++)
                mma_f16(acc[mi][ni],
                        fa[par][mi][0], fa[par][mi][1], fa[par][mi][2], fa[par][mi][3],
                        fb[par][ni][0], fb[par][ni][1]);
    };

    issue(0); issue(1);
    asm volatile("cp.async.wait_group 1;" ::: "memory");
    __syncthreads();                      // stage 0 visible to all warps
    ldfrag(0, sbase, 0);

    for (int c = 0; c < NCHUNK; c++) {
        const uint32_t st = sbase + (c & 1) * STAGEB;
        #pragma unroll
        for (int ks = 0; ks < 4; ks++) {
            if (ks < 3) ldfrag((ks + 1) & 1, st, ks + 1);
            domma(ks & 1);
        }
        __syncthreads();                  // all warps done reading stage c
        if (c + 1 < NCHUNK) {
            if (c + 2 < NCHUNK) {
                issue(c + 2);
                asm volatile("cp.async.wait_group 1;" ::: "memory");
            } else {
                asm volatile("cp.async.wait_group 0;" ::: "memory");
            }
            __syncthreads();              // publish stage c+1
            ldfrag(0, sbase + ((c + 1) & 1) * STAGEB, 0);
        }
    }

    // ------------- epilogue: squared-distance two-way mining -------------
    const float* rsq = (const float*)(sb + OFF_RSQ);
    const int*   rlb = (const int*)(sb + OFF_RLB);
    const float* csq = (const float*)(sb + OFF_CSQ);
    const int*   clb = (const int*)(sb + OFF_CLB);

    const float INF = __int_as_float(0x7f800000);

    float apv[2][2], anv[2][2];
    float sqr[2][2]; int lbr[2][2];
    #pragma unroll
    for (int mi = 0; mi < 2; mi++)
        #pragma unroll
        for (int h = 0; h < 2; h++) {
            apv[mi][h] = 0.f;
            anv[mi][h] = INF;
            int r = wm * 32 + mi * 16 + h * 8 + (lane >> 2);
            sqr[mi][h] = rsq[r];
            lbr[mi][h] = rlb[r];
        }

    #pragma unroll
    for (int ni = 0; ni < 8; ni++) {
        const int jl = wn * 64 + ni * 8 + (lane & 3) * 2;
        float cap[2] = {0.f, 0.f};
        float can[2] = {INF, INF};
        #pragma unroll
        for (int e = 0; e < 2; e++) {
            const float sqj = csq[jl + e];
            const int   lj  = clb[jl + e];
            #pragma unroll
            for (int mi = 0; mi < 2; mi++)
                #pragma unroll
                for (int h = 0; h < 2; h++) {
                    float d2 = fmaf(-2.f, acc[mi][ni][h * 2 + e], sqr[mi][h] + sqj);
                    d2 = fmaxf(d2, 0.f);       // clamp; sqrt deferred (monotone)
                    if (lbr[mi][h] == lj) {
                        apv[mi][h] = fmaxf(apv[mi][h], d2);
                        cap[e] = fmaxf(cap[e], d2);
                    } else {
                        anv[mi][h] = fminf(anv[mi][h], d2);
                        can[e] = fminf(can[e], d2);
                    }
                }
        }
        // column mining (mirrored extras are idempotent for max/min)
        #pragma unroll
        for (int e = 0; e < 2; e++) {
            #pragma unroll
            for (int o = 4; o <= 16; o <<= 1) {
                cap[e] = fmaxf(cap[e], __shfl_xor_sync(0xffffffffu, cap[e], o));
                can[e] = fminf(can[e], __shfl_xor_sync(0xffffffffu, can[e], o));
            }
            if (lane < 4) {
                int col = colBase + wn * 64 + ni * 8 + lane * 2 + e;
                atomicMax((int*)&g_ap[col], __float_as_int(cap[e]));
                atomicMin((int*)&g_an[col], __float_as_int(can[e]));
            }
        }
    }

    // row-side reduction over 4 lanes sharing each row
    #pragma unroll
    for (int mi = 0; mi < 2; mi++)
        #pragma unroll
        for (int h = 0; h < 2; h++) {
            #pragma unroll
            for (int o = 1; o <= 2; o <<= 1) {
                apv[mi][h] = fmaxf(apv[mi][h], __shfl_xor_sync(0xffffffffu, apv[mi][h], o));
                anv[mi][h] = fminf(anv[mi][h], __shfl_xor_sync(0xffffffffu, anv[mi][h], o));
            }
        }
    if ((lane & 3) == 0) {
        #pragma unroll
        for (int mi = 0; mi < 2; mi++)
            #pragma unroll
            for (int h = 0; h < 2; h++) {
                int row = rowBase + wm * 32 + mi * 16 + h * 8 + (lane >> 2);
                atomicMax((int*)&g_ap[row], __float_as_int(apv[mi][h]));
                atomicMin((int*)&g_an[row], __float_as_int(anv[mi][h]));
            }
    }

    // ------------- fused final loss: last CTA reduces (sqrt here) -------------
    __syncthreads();
    __shared__ unsigned s_rank;
    if (tid == 0) {
        __threadfence();
        s_rank = atomicAdd(&g_done, 1u);
    }
    __syncthreads();
    if (s_rank == NBLK - 1) {
        __threadfence();
        float* ssum = (float*)(sb);
        int*   scnt = (int*)(sb + 1024);
        float s2 = 0.f; int c = 0;
        for (int i = tid; i < N; i += 128) {
            float ap2 = g_ap[i];
            float an2 = g_an[i];
            if (ap2 > 0.f && isfinite(an2)) {
                c++;
                float v = sqrtf(ap2) - sqrtf(an2) + MARGIN;
                s2 += v > 0.f ? v : 0.f;
            }
        }
        ssum[tid] = s2;
        scnt[tid] = c;
        __syncthreads();
        for (int o = 64; o; o >>= 1) {
            if (tid < o) {
                ssum[tid] += ssum[tid + o];
                scnt[tid] += scnt[tid + o];
            }
            __syncthreads();
        }
        if (tid == 0) {
            int n = scnt[0];
            out[0] = (n > 0) ? (ssum[0] / (float)n) : 0.f;
        }
    }
}

// ---------------------------------------------------------------------------
extern "C" void kernel_launch(void* const* d_in, const int* in_sizes, int n_in,
                              void* d_out, int out_size) {
    const float* F   = (const float*)d_in[0];
    const int*   lab = (const int*)d_in[1];
    float* out = (float*)d_out;

    cudaFuncSetAttribute(mma_mine_kernel,
                         cudaFuncAttributeMaxDynamicSharedMemorySize, SMEM_BYTES);

    prep_kernel<<<N / 8, 256>>>(F, lab);
    mma_mine_kernel<<<NBLK, 128, SMEM_BYTES>>>(out);
}